// round 10
// baseline (speedup 1.0000x reference)
#include <cuda_runtime.h>
#include <cstddef>

// ---------------------------------------------------------------------------
// Differentiable JPEG (quality=75), fused, thread-per-row, pass-fused phases.
//  Phase A: load RGB (coalesced float4), Y row -> dct8 in registers -> store
//           transformed row to smem. Chroma 2x2 pool via in-thread horizontal
//           sums + shfl_down(8) vertical partner; pooled chroma -> smem.
//  Phase B: Y blocks: pass2 only (column-local quantize pipeline, no syncs).
//           Chroma blocks: full 3-pass pipeline (pass1/2/3, 2 syncwarps).
//  Phase C: read E-row, final dct8 in registers, upsample chroma, RGB, STG.
// Shared pitch 9/72 -> all smem access patterns proven conflict-free.
// qt tables: compile-time, staged global->smem (no constant-port LDC replays).
// Division: rcp-mul + FMA Newton residual (bit-identical to RN FDIV here).
// ---------------------------------------------------------------------------

#define THREADS 256
#define BPITCH 72
#define RPITCH 9

// ---- Compile-time scaled quant tables (quality=75 -> s=50 -> t=(q+1)/2). ----
struct QTab { float q[64]; float r[64]; };
struct QTabs { QTab y; QTab c; };

constexpr QTab make_tab(const int (&b)[64]) {
  QTab t{};
  for (int i = 0; i < 64; i++) {
    int n = b[i] + 1;                       // scaled numerator: t = n/2 exactly
    double v = 0.0;
    if ((n & 1) == 0) {
      v = (double)(n / 2);                  // integer -> diff_round is identity
    } else {
      long k = n / 2;                       // t = k + 0.5 (exact tie)
      double tt = (double)k + 0.5;
      double rr = ((k & 1) == 0) ? (double)k : (double)(k + 1);  // half-to-even
      double d  = tt - rr;
      v = rr + d * d * d;                   // diff_round
    }
    if (v < 1.0) v = 1.0;
    if (v > 255.0) v = 255.0;
    t.q[i] = (float)v;                      // exact (values are k + m/8)
    t.r[i] = (float)(1.0 / (double)((float)v));  // correctly-rounded fp32 recip
  }
  return t;
}

constexpr int QY_B[64] = {
  16,11,10,16,24,40,51,61,
  12,12,14,19,26,58,60,55,
  14,13,16,24,40,57,69,56,
  14,17,22,29,51,87,80,62,
  18,22,37,56,68,109,103,77,
  24,35,55,64,81,104,113,92,
  49,64,78,87,103,121,120,101,
  72,92,95,98,112,100,103,99 };

constexpr int QC_B[64] = {
  17,18,24,47,99,99,99,99,
  18,21,26,66,99,99,99,99,
  24,26,56,99,99,99,99,99,
  47,66,99,99,99,99,99,99,
  99,99,99,99,99,99,99,99,
  99,99,99,99,99,99,99,99,
  99,99,99,99,99,99,99,99,
  99,99,99,99,99,99,99,99 };

__device__ const QTabs G_QT = { make_tab(QY_B), make_tab(QC_B) };

__device__ __forceinline__ float diff_round(float x) {
  float r = rintf(x);           // round half to even, matches jnp.round
  float d = x - r;
  return fmaf(d * d, d, r);
}

// out[u] = sum_k M[u,k] a[k] -- 8-pt DCT-II via even/odd butterfly (~36 ops).
__device__ __forceinline__ void dct8(const float* __restrict__ a, float* __restrict__ out) {
  const float S  = 0.3535533905932738f;
  const float A  = 0.4619397662556434f, B  = 0.1913417161825449f;
  const float c1 = 0.4903926402016152f, c3 = 0.4157348061512726f;
  const float c5 = 0.2777851165098011f, c7 = 0.0975451610080641f;
  float e0 = a[0] + a[7], e1 = a[1] + a[6], e2 = a[2] + a[5], e3 = a[3] + a[4];
  float o0 = a[0] - a[7], o1 = a[1] - a[6], o2 = a[2] - a[5], o3 = a[3] - a[4];
  float q0 = e0 + e3, q1 = e1 + e2;
  float r0 = e0 - e3, r1 = e1 - e2;
  out[0] = S * (q0 + q1);
  out[4] = S * (q0 - q1);
  out[2] = fmaf(A, r0,  B * r1);
  out[6] = fmaf(B, r0, -A * r1);
  out[1] = fmaf(c1, o0, fmaf( c3, o1, fmaf( c5, o2,  c7 * o3)));
  out[3] = fmaf(c3, o0, fmaf(-c7, o1, fmaf(-c1, o2, -c5 * o3)));
  out[5] = fmaf(c5, o0, fmaf(-c1, o1, fmaf( c7, o2,  c3 * o3)));
  out[7] = fmaf(c7, o0, fmaf(-c5, o1, fmaf( c3, o2, -c1 * o3)));
}

__device__ __forceinline__ void quant8(float* __restrict__ d,
                                       const float* __restrict__ qcol,
                                       const float* __restrict__ rcol) {
#pragma unroll
  for (int u = 0; u < 8; u++) {
    float q  = qcol[u];
    float r  = rcol[u];
    float t0 = d[u] * r;                 // refined division == RN d/q
    float e  = fmaf(-t0, q, d[u]);
    float tt = fmaf(e, r, t0);
    d[u] = diff_round(tt) * q;
  }
}

// Y pass2: column-local, fully col-partitioned -> no syncwarp needed.
__device__ __forceinline__ void pass2_col(float* __restrict__ base, int t,
                                          const float* __restrict__ qcol,
                                          const float* __restrict__ rcol) {
  float c[8];
#pragma unroll
  for (int k = 0; k < 8; k++) c[k] = base[k * RPITCH + t];
  float d[8]; dct8(c, d);
  quant8(d, qcol, rcol);
  float e[8]; dct8(d, e);
#pragma unroll
  for (int u = 0; u < 8; u++) base[u * RPITCH + t] = e[u];
}

// Chroma: full 3-pass pipeline (pass1 rows, pass2 cols+quant, pass3 rows).
__device__ __forceinline__ void process_full(float* __restrict__ base, int t,
                                             const float* __restrict__ qcol,
                                             const float* __restrict__ rcol) {
  float a[8];
#pragma unroll
  for (int k = 0; k < 8; k++) a[k] = base[t * RPITCH + k];
  float w[8]; dct8(a, w);
#pragma unroll
  for (int k = 0; k < 8; k++) base[t * RPITCH + k] = w[k];
  __syncwarp();
  pass2_col(base, t, qcol, rcol);
  __syncwarp();
  float rr[8];
#pragma unroll
  for (int k = 0; k < 8; k++) rr[k] = base[t * RPITCH + k];
  float o[8]; dct8(rr, o);
#pragma unroll
  for (int k = 0; k < 8; k++) base[t * RPITCH + k] = o[k];
}

// Chroma plane indexer (32x32 plane, 16 blocks, pitch 9/72).
__device__ __forceinline__ int cidx(int cy, int cx) {
  return ((cy >> 3) * 4 + (cx >> 3)) * BPITCH + (cy & 7) * RPITCH + (cx & 7);
}

__global__ __launch_bounds__(THREADS, 5)
void jpeg_fused_kernel(const float* __restrict__ in, float* __restrict__ out, int H, int W) {
  __shared__ float sY[64 * BPITCH];   // 64 Y blocks (holds X*dct -> then E)
  __shared__ float sC[32 * BPITCH];   // 16 Cb blocks then 16 Cr blocks
  __shared__ QTabs sQT;               // staged quant tables (1 KB)

  const int tid = threadIdx.x;
  const int b = blockIdx.z;
  const size_t plane = (size_t)H * W;
  const float* __restrict__ Rp = in + (size_t)b * 3 * plane;
  const float* __restrict__ Gp = Rp + plane;
  const float* __restrict__ Bp = Gp + plane;
  float* __restrict__ Ro = out + (size_t)b * 3 * plane;
  float* __restrict__ Go = Ro + plane;
  float* __restrict__ Bo = Go + plane;

  const int ox = blockIdx.x * 64;
  const int oy = blockIdx.y * 64;

  // Stage quant tables: 64 threads x float4 = 1 KB, coalesced LDG.
  if (tid < 64) {
    ((float4*)&sQT)[tid] = ((const float4*)&G_QT)[tid];
  }

  // ---- Phase A: load + Y pass1 + chroma pooling. 512 row-units, 2/thread. ----
  // Unit v -> tile row r = v>>3 (0..63), col-chunk c = v&7 (8 pixels).
  // Warp = 4 consecutive rows x full 64 cols -> coalesced; vertical chroma
  // partner (row r+1, r even) is lane+8, always in-warp.
#pragma unroll
  for (int i = 0; i < 2; i++) {
    const int v = tid + i * THREADS;
    const int r = v >> 3, c = v & 7;
    const size_t go = (size_t)(oy + r) * W + (ox + 8 * c);

    float4 rA = *(const float4*)(Rp + go), rB = *(const float4*)(Rp + go + 4);
    float4 gA = *(const float4*)(Gp + go), gB = *(const float4*)(Gp + go + 4);
    float4 bA = *(const float4*)(Bp + go), bB = *(const float4*)(Bp + go + 4);

    const float* rr = (const float*)&rA;   // rA,rB contiguous in memory order
    const float* gg = (const float*)&gA;
    const float* bb = (const float*)&bA;
    float rpix[8], gpix[8], bpix[8];
#pragma unroll
    for (int k = 0; k < 4; k++) { rpix[k] = rr[k]; gpix[k] = gg[k]; bpix[k] = bb[k]; }
    rpix[4]=rB.x; rpix[5]=rB.y; rpix[6]=rB.z; rpix[7]=rB.w;
    gpix[4]=gB.x; gpix[5]=gB.y; gpix[6]=gB.z; gpix[7]=gB.w;
    bpix[4]=bB.x; bpix[5]=bB.y; bpix[6]=bB.z; bpix[7]=bB.w;

    float y8[8], cbh[4], crh[4];
#pragma unroll
    for (int j = 0; j < 4; j++) { cbh[j] = 0.0f; crh[j] = 0.0f; }
#pragma unroll
    for (int k = 0; k < 8; k++) {
      float rv = rpix[k] * 255.0f, gv = gpix[k] * 255.0f, bv = bpix[k] * 255.0f;
      float yv  =  0.299f    * rv + 0.587f    * gv + 0.114f    * bv;
      float cbv = -0.168736f * rv - 0.331264f * gv + 0.5f      * bv;
      float crv =  0.5f      * rv - 0.418688f * gv - 0.081312f * bv;
      y8[k] = yv - 128.0f;               // +/-128 chroma shift cancels in ref
      cbh[k >> 1] += cbv; crh[k >> 1] += crv;
    }

    // Vertical chroma partner: row r+1 lives at lane+8 in this warp.
#pragma unroll
    for (int j = 0; j < 4; j++) {
      float cbd = __shfl_down_sync(0xffffffffu, cbh[j], 8);
      float crd = __shfl_down_sync(0xffffffffu, crh[j], 8);
      if ((r & 1) == 0) {
        const int cy = r >> 1, cx = 4 * c + j;
        sC[cidx(cy, cx)]               = (cbh[j] + cbd) * 0.25f;
        sC[16 * BPITCH + cidx(cy, cx)] = (crh[j] + crd) * 0.25f;
      }
    }

    // Y pass1 in registers, store transformed row (conflict-free pattern).
    float w8[8]; dct8(y8, w8);
    float* yb = sY + ((r >> 3) * 8 + c) * BPITCH + (r & 7) * RPITCH;
#pragma unroll
    for (int k = 0; k < 8; k++) yb[k] = w8[k];
  }
  __syncthreads();

  // ---- Phase B: Y pass2 (2 rounds) + chroma full pipeline (1 round). ----
  {
    const int t   = tid & 7;
    const int grp = tid >> 3;

    float qcol[8], rcol[8];
#pragma unroll
    for (int u = 0; u < 8; u++) {       // conflict-free LDS hoist
      qcol[u] = sQT.y.q[u * 8 + t];
      rcol[u] = sQT.y.r[u * 8 + t];
    }
    pass2_col(sY + grp * BPITCH, t, qcol, rcol);
    pass2_col(sY + (32 + grp) * BPITCH, t, qcol, rcol);
#pragma unroll
    for (int u = 0; u < 8; u++) {
      qcol[u] = sQT.c.q[u * 8 + t];
      rcol[u] = sQT.c.r[u * 8 + t];
    }
    process_full(sC + grp * BPITCH, t, qcol, rcol);  // grp 0-15 Cb, 16-31 Cr
  }
  __syncthreads();

  // ---- Phase C: Y pass3 in registers + chroma upsample + RGB + STG. ----
  const float inv255 = 1.0f / 255.0f;
#pragma unroll
  for (int i = 0; i < 2; i++) {
    const int v = tid + i * THREADS;
    const int r = v >> 3, c = v & 7;
    const size_t go = (size_t)(oy + r) * W + (ox + 8 * c);

    const float* yb = sY + ((r >> 3) * 8 + c) * BPITCH + (r & 7) * RPITCH;
    float e8[8];
#pragma unroll
    for (int k = 0; k < 8; k++) e8[k] = yb[k];
    float rec[8]; dct8(e8, rec);

    const int cy = r >> 1;
    float cb4[4], cr4[4];
#pragma unroll
    for (int j = 0; j < 4; j++) {
      cb4[j] = sC[cidx(cy, 4 * c + j)];                 // broadcast pairs, CF
      cr4[j] = sC[16 * BPITCH + cidx(cy, 4 * c + j)];
    }

    float4 r4[2], g4[2], b4[2];
    float* rr = (float*)r4; float* gg = (float*)g4; float* bb = (float*)b4;
#pragma unroll
    for (int k = 0; k < 8; k++) {
      float yv = rec[k] + 128.0f;
      float cb = cb4[k >> 1], cr = cr4[k >> 1];
      rr[k] = __saturatef((yv + 1.402f * cr) * inv255);
      gg[k] = __saturatef((yv - 0.344136f * cb - 0.714136f * cr) * inv255);
      bb[k] = __saturatef((yv + 1.772f * cb) * inv255);
    }
    *(float4*)(Ro + go)     = r4[0];
    *(float4*)(Ro + go + 4) = r4[1];
    *(float4*)(Go + go)     = g4[0];
    *(float4*)(Go + go + 4) = g4[1];
    *(float4*)(Bo + go)     = b4[0];
    *(float4*)(Bo + go + 4) = b4[1];
  }
}

extern "C" void kernel_launch(void* const* d_in, const int* in_sizes, int n_in,
                              void* d_out, int out_size) {
  const float* img = (const float*)d_in[0];
  float* out = (float*)d_out;
  const int H = 1024, W = 1024;
  const int B = in_sizes[0] / (3 * H * W);
  dim3 grid(W / 64, H / 64, B);
  dim3 block(THREADS);
  jpeg_fused_kernel<<<grid, block>>>(img, out, H, W);
}

// round 11
// speedup vs baseline: 1.1403x; 1.1403x over previous
#include <cuda_runtime.h>
#include <cstddef>

// ---------------------------------------------------------------------------
// Differentiable JPEG (quality=75), fused, thread-per-row.  [R9 structure]
// CTA = 64x64 pixel tile = 96 8x8 blocks (64 Y + 32 chroma).
// 256 threads = 32 groups of 8; each group does one block per round (3 rounds).
// Per block: rec = M ( diff_round( (M (X M^T)) / qt ) * qt ) M^T as 4 identical
// 8-pt butterflies, 2 smem transposes. qt + reciprocal: compile-time tables in
// GLOBAL memory, staged to smem (constant-port divergent-LDC replays killed),
// hoisted to registers once per table via conflict-free LDS.
// Division = rcp-mul + one FMA Newton residual (bit-identical rel_err vs FDIV).
// Shared pitch 9/72 -> conflict-free row AND column access.
// R11 change: __launch_bounds__(256,6) -> 6 CTAs/SM (occupancy 54% -> 75% cap).
// ---------------------------------------------------------------------------

#define THREADS 256
#define BPITCH 72
#define RPITCH 9

// ---- Compile-time scaled quant tables (quality=75 -> s=50 -> t=(q+1)/2). ----
struct QTab { float q[64]; float r[64]; };
struct QTabs { QTab y; QTab c; };

constexpr QTab make_tab(const int (&b)[64]) {
  QTab t{};
  for (int i = 0; i < 64; i++) {
    int n = b[i] + 1;                       // scaled numerator: t = n/2 exactly
    double v = 0.0;
    if ((n & 1) == 0) {
      v = (double)(n / 2);                  // integer -> diff_round is identity
    } else {
      long k = n / 2;                       // t = k + 0.5 (exact tie)
      double tt = (double)k + 0.5;
      double rr = ((k & 1) == 0) ? (double)k : (double)(k + 1);  // half-to-even
      double d  = tt - rr;
      v = rr + d * d * d;                   // diff_round
    }
    if (v < 1.0) v = 1.0;
    if (v > 255.0) v = 255.0;
    t.q[i] = (float)v;                      // exact (values are k + m/8)
    t.r[i] = (float)(1.0 / (double)((float)v));  // correctly-rounded fp32 recip
  }
  return t;
}

constexpr int QY_B[64] = {
  16,11,10,16,24,40,51,61,
  12,12,14,19,26,58,60,55,
  14,13,16,24,40,57,69,56,
  14,17,22,29,51,87,80,62,
  18,22,37,56,68,109,103,77,
  24,35,55,64,81,104,113,92,
  49,64,78,87,103,121,120,101,
  72,92,95,98,112,100,103,99 };

constexpr int QC_B[64] = {
  17,18,24,47,99,99,99,99,
  18,21,26,66,99,99,99,99,
  24,26,56,99,99,99,99,99,
  47,66,99,99,99,99,99,99,
  99,99,99,99,99,99,99,99,
  99,99,99,99,99,99,99,99,
  99,99,99,99,99,99,99,99,
  99,99,99,99,99,99,99,99 };

// Global memory (LDG path, coalesced) -- NOT __constant__: divergent LDC
// replays on the half-rate constant port were serializing R7/R8.
__device__ const QTabs G_QT = { make_tab(QY_B), make_tab(QC_B) };

__device__ __forceinline__ float diff_round(float x) {
  float r = rintf(x);           // round half to even, matches jnp.round
  float d = x - r;
  return fmaf(d * d, d, r);
}

// out[u] = sum_k M[u,k] a[k] -- 8-pt DCT-II via even/odd butterfly (~36 ops).
__device__ __forceinline__ void dct8(const float* __restrict__ a, float* __restrict__ out) {
  const float S  = 0.3535533905932738f;
  const float A  = 0.4619397662556434f, B  = 0.1913417161825449f;
  const float c1 = 0.4903926402016152f, c3 = 0.4157348061512726f;
  const float c5 = 0.2777851165098011f, c7 = 0.0975451610080641f;
  float e0 = a[0] + a[7], e1 = a[1] + a[6], e2 = a[2] + a[5], e3 = a[3] + a[4];
  float o0 = a[0] - a[7], o1 = a[1] - a[6], o2 = a[2] - a[5], o3 = a[3] - a[4];
  float q0 = e0 + e3, q1 = e1 + e2;
  float r0 = e0 - e3, r1 = e1 - e2;
  out[0] = S * (q0 + q1);
  out[4] = S * (q0 - q1);
  out[2] = fmaf(A, r0,  B * r1);
  out[6] = fmaf(B, r0, -A * r1);
  out[1] = fmaf(c1, o0, fmaf( c3, o1, fmaf( c5, o2,  c7 * o3)));
  out[3] = fmaf(c3, o0, fmaf(-c7, o1, fmaf(-c1, o2, -c5 * o3)));
  out[5] = fmaf(c5, o0, fmaf(-c1, o1, fmaf( c7, o2,  c3 * o3)));
  out[7] = fmaf(c7, o0, fmaf(-c5, o1, fmaf( c3, o2, -c1 * o3)));
}

// Full block pipeline, thread t of an 8-thread group. Only 2 syncwarps.
// qcol/rcol: this thread's quant column (qt[u][t]) and its fp32 reciprocal.
__device__ __forceinline__ void process_block(float* __restrict__ base, int t,
                                              const float* __restrict__ qcol,
                                              const float* __restrict__ rcol) {
  // Pass 1 (row-local): W[t,:] = row t of (X M^T).
  float a[8];
#pragma unroll
  for (int k = 0; k < 8; k++) a[k] = base[t * RPITCH + k];
  float w[8]; dct8(a, w);
#pragma unroll
  for (int k = 0; k < 8; k++) base[t * RPITCH + k] = w[k];   // own row
  __syncwarp();

  // Pass 2 (column-local): D[:,t] = M W[:,t]; quantize; E[:,t] = M deq[:,t].
  float c[8];
#pragma unroll
  for (int k = 0; k < 8; k++) c[k] = base[k * RPITCH + t];
  float d[8]; dct8(c, d);
#pragma unroll
  for (int u = 0; u < 8; u++) {
    float q  = qcol[u];
    float r  = rcol[u];
    // Refined division: t0 + r*(d - t0*q) == d/q rounded-to-nearest (~0.55 ulp).
    float t0 = d[u] * r;
    float e  = fmaf(-t0, q, d[u]);
    float tt = fmaf(e, r, t0);
    d[u] = diff_round(tt) * q;
  }
  float e8[8]; dct8(d, e8);
#pragma unroll
  for (int u = 0; u < 8; u++) base[u * RPITCH + t] = e8[u];  // own column
  __syncwarp();

  // Pass 3 (row-local): rec[t,:] = row t of (E M^T).
  float rr[8];
#pragma unroll
  for (int k = 0; k < 8; k++) rr[k] = base[t * RPITCH + k];
  float o[8]; dct8(rr, o);
#pragma unroll
  for (int k = 0; k < 8; k++) base[t * RPITCH + k] = o[k];   // own row
}

// Shared indexers (block pitch 72, row pitch 9).
__device__ __forceinline__ int yidx(int ly, int lx) {
  return ((ly >> 3) * 8 + (lx >> 3)) * BPITCH + (ly & 7) * RPITCH + (lx & 7);
}
__device__ __forceinline__ int cidx(int ly, int lx) {
  return ((ly >> 3) * 4 + (lx >> 3)) * BPITCH + (ly & 7) * RPITCH + (lx & 7);
}

__global__ __launch_bounds__(THREADS, 6)
void jpeg_fused_kernel(const float* __restrict__ in, float* __restrict__ out, int H, int W) {
  __shared__ float sY[64 * BPITCH];   // 64 Y blocks
  __shared__ float sC[32 * BPITCH];   // 16 Cb blocks then 16 Cr blocks
  __shared__ QTabs sQT;               // staged quant tables (1 KB)

  const int tid = threadIdx.x;
  const int b = blockIdx.z;
  const size_t plane = (size_t)H * W;
  const float* __restrict__ Rp = in + (size_t)b * 3 * plane;
  const float* __restrict__ Gp = Rp + plane;
  const float* __restrict__ Bp = Gp + plane;
  float* __restrict__ Ro = out + (size_t)b * 3 * plane;
  float* __restrict__ Go = Ro + plane;
  float* __restrict__ Bo = Go + plane;

  const int ox = blockIdx.x * 64;
  const int oy = blockIdx.y * 64;

  // Stage quant tables: 64 threads x float4 = 1 KB, coalesced LDG from global.
  if (tid < 64) {
    ((float4*)&sQT)[tid] = ((const float4*)&G_QT)[tid];
  }

  // ---- Load phase: 4x2 pixel units (float4 x 2 rows). 512 units, 2/thread. ----
#pragma unroll
  for (int i = 0; i < 2; i++) {
    const int u = tid + i * THREADS;
    const int ux = u & 15, uy = u >> 4;          // 16 units wide, 32 tall
    const int px = ox + 4 * ux;
    const int py = oy + 2 * uy;
    const size_t o0 = (size_t)py * W + px;
    const size_t o1 = o0 + W;

    float4 r4[2] = { *(const float4*)(Rp + o0), *(const float4*)(Rp + o1) };
    float4 g4[2] = { *(const float4*)(Gp + o0), *(const float4*)(Gp + o1) };
    float4 b4[2] = { *(const float4*)(Bp + o0), *(const float4*)(Bp + o1) };

    const float* rr = (const float*)r4;
    const float* gg = (const float*)g4;
    const float* bb = (const float*)b4;

    float cbs[2] = {0.0f, 0.0f}, crs[2] = {0.0f, 0.0f};
#pragma unroll
    for (int k = 0; k < 8; k++) {               // k = row*4 + col
      const int row = k >> 2, col = k & 3;
      float rv = rr[k] * 255.0f, gv = gg[k] * 255.0f, bv = bb[k] * 255.0f;
      float yv  =  0.299f    * rv + 0.587f    * gv + 0.114f    * bv;
      float cbv = -0.168736f * rv - 0.331264f * gv + 0.5f      * bv;
      float crv =  0.5f      * rv - 0.418688f * gv - 0.081312f * bv;
      const int h = col >> 1;                   // which 2x2 within the 4x2 unit
      cbs[h] += cbv; crs[h] += crv;
      sY[yidx(2 * uy + row, 4 * ux + col)] = yv - 128.0f;  // +/-128 chroma shift cancels
    }
    sC[cidx(uy, 2 * ux)]                   = cbs[0] * 0.25f;
    sC[cidx(uy, 2 * ux + 1)]               = cbs[1] * 0.25f;
    sC[16 * BPITCH + cidx(uy, 2 * ux)]     = crs[0] * 0.25f;
    sC[16 * BPITCH + cidx(uy, 2 * ux + 1)] = crs[1] * 0.25f;
  }
  __syncthreads();

  // ---- Process phase: 32 groups of 8 threads, 3 rounds. ----
  {
    const int t   = tid & 7;
    const int grp = tid >> 3;

    // Hoist this thread's qt column to registers via conflict-free LDS
    // (pattern u*8+t: 8 distinct banks, 4-lane broadcast each).
    float qcol[8], rcol[8];
#pragma unroll
    for (int u = 0; u < 8; u++) {
      qcol[u] = sQT.y.q[u * 8 + t];
      rcol[u] = sQT.y.r[u * 8 + t];
    }
    process_block(sY + grp * BPITCH, t, qcol, rcol);
    process_block(sY + (32 + grp) * BPITCH, t, qcol, rcol);
#pragma unroll
    for (int u = 0; u < 8; u++) {
      qcol[u] = sQT.c.q[u * 8 + t];
      rcol[u] = sQT.c.r[u * 8 + t];
    }
    process_block(sC + grp * BPITCH, t, qcol, rcol);  // grp 0-15 Cb, 16-31 Cr
  }
  __syncthreads();

  // ---- Output phase: 4x2 units, upsample chroma, YCbCr->RGB, saturate. ----
  const float inv255 = 1.0f / 255.0f;
#pragma unroll
  for (int i = 0; i < 2; i++) {
    const int u = tid + i * THREADS;
    const int ux = u & 15, uy = u >> 4;
    const int px = ox + 4 * ux;
    const int py = oy + 2 * uy;
    const size_t o0 = (size_t)py * W + px;
    const size_t o1 = o0 + W;

    float cbv[2], crv[2];
    cbv[0] = sC[cidx(uy, 2 * ux)];
    cbv[1] = sC[cidx(uy, 2 * ux + 1)];
    crv[0] = sC[16 * BPITCH + cidx(uy, 2 * ux)];
    crv[1] = sC[16 * BPITCH + cidx(uy, 2 * ux + 1)];

    float4 r4[2], g4[2], b4[2];
    float* rr = (float*)r4; float* gg = (float*)g4; float* bb = (float*)b4;
#pragma unroll
    for (int k = 0; k < 8; k++) {
      const int row = k >> 2, col = k & 3;
      const int h = col >> 1;
      float yv = sY[yidx(2 * uy + row, 4 * ux + col)] + 128.0f;
      float cb = cbv[h], cr = crv[h];
      // saturate(v*inv255) == clip(clip(v,0,255)/255, 0, 1) (<=1ulp, continuous)
      rr[k] = __saturatef((yv + 1.402f * cr) * inv255);
      gg[k] = __saturatef((yv - 0.344136f * cb - 0.714136f * cr) * inv255);
      bb[k] = __saturatef((yv + 1.772f * cb) * inv255);
    }
    *(float4*)(Ro + o0) = r4[0];
    *(float4*)(Ro + o1) = r4[1];
    *(float4*)(Go + o0) = g4[0];
    *(float4*)(Go + o1) = g4[1];
    *(float4*)(Bo + o0) = b4[0];
    *(float4*)(Bo + o1) = b4[1];
  }
}

extern "C" void kernel_launch(void* const* d_in, const int* in_sizes, int n_in,
                              void* d_out, int out_size) {
  const float* img = (const float*)d_in[0];
  float* out = (float*)d_out;
  const int H = 1024, W = 1024;
  const int B = in_sizes[0] / (3 * H * W);
  dim3 grid(W / 64, H / 64, B);
  dim3 block(THREADS);
  jpeg_fused_kernel<<<grid, block>>>(img, out, H, W);
}